// round 1
// baseline (speedup 1.0000x reference)
#include <cuda_runtime.h>
#include <math.h>

#define NE   12
#define HDIM 2048
#define FDIM 1280
#define TMAX 4096
#define BK   16
#define BM   64
#define PAD  68   // padded smem row (floats), 16B-aligned rows, reduced bank conflicts

// -------- device scratch (alloc-free rule: __device__ globals) --------
__device__ int   g_count[NE];
__device__ int   g_tok[NE * TMAX];
__device__ float g_wt[NE * TMAX];
__device__ float g_h[(size_t)NE * TMAX * FDIM];   // ~252 MB SwiGLU activations

// -------- reset per-launch state --------
__global__ void k_zero() {
    if (threadIdx.x < NE) g_count[threadIdx.x] = 0;
}

// -------- gating: logits -> top2 -> per-expert token lists --------
__global__ void k_gate(const float* __restrict__ x, const float* __restrict__ gw) {
    int t   = blockIdx.x;
    int tid = threadIdx.x;                 // 128 threads
    const float* xr = x + (size_t)t * HDIM;

    float acc[NE];
#pragma unroll
    for (int e = 0; e < NE; e++) acc[e] = 0.f;

    for (int k = tid; k < HDIM; k += 128) {
        float xv = xr[k];
#pragma unroll
        for (int e = 0; e < NE; e++) acc[e] += xv * gw[e * HDIM + k];
    }

    __shared__ float s[NE][128];
#pragma unroll
    for (int e = 0; e < NE; e++) s[e][tid] = acc[e];
    __syncthreads();

    if (tid < NE) {
        float v = 0.f;
        for (int i = 0; i < 128; i++) v += s[tid][i];
        s[tid][0] = v;
    }
    __syncthreads();

    if (tid == 0) {
        float l[NE];
#pragma unroll
        for (int e = 0; e < NE; e++) l[e] = s[e][0];
        // argmax (strict > keeps lowest index on ties, matching jax top_k)
        int i0 = 0;
#pragma unroll
        for (int e = 1; e < NE; e++) if (l[e] > l[i0]) i0 = e;
        int i1 = (i0 == 0) ? 1 : 0;
#pragma unroll
        for (int e = 0; e < NE; e++) if (e != i0 && l[e] > l[i1]) i1 = e;
        // softmax denominator cancels under top-2 renorm:
        float w0 = 1.f / (1.f + expf(l[i1] - l[i0]));
        float w1 = 1.f - w0;

        int p0 = atomicAdd(&g_count[i0], 1);
        g_tok[i0 * TMAX + p0] = t;  g_wt[i0 * TMAX + p0] = w0;
        int p1 = atomicAdd(&g_count[i1], 1);
        g_tok[i1 * TMAX + p1] = t;  g_wt[i1 * TMAX + p1] = w1;
    }
}

// -------- stage 1: h = silu(X@W1^T) * (X@W3^T), grouped by expert --------
__global__ void __launch_bounds__(256)
k_ffn1(const float* __restrict__ x,
       const float* __restrict__ w1, const float* __restrict__ w3) {
    int e   = blockIdx.z;
    int cnt = g_count[e];
    int r0  = blockIdx.y * BM;
    if (r0 >= cnt) return;                       // past this expert's rows
    int c0  = blockIdx.x * BM;

    __shared__ __align__(16) float Xs[BK][PAD];
    __shared__ __align__(16) float B1s[BK][PAD];
    __shared__ __align__(16) float B3s[BK][PAD];
    __shared__ int toks[BM];

    int tid = threadIdx.x;                       // 256
    if (tid < BM) {
        int rr = r0 + tid;
        toks[tid] = g_tok[e * TMAX + (rr < cnt ? rr : 0)];
    }
    __syncthreads();

    int lr = tid >> 2;              // 0..63 : tile row (or B col)
    int lk = (tid & 3) << 2;        // 0,4,8,12 : k offset (float4)

    const float* xp  = x  + (size_t)toks[lr] * HDIM + lk;
    const float* b1p = w1 + (size_t)e * FDIM * HDIM + (size_t)(c0 + lr) * HDIM + lk;
    const float* b3p = w3 + (size_t)e * FDIM * HDIM + (size_t)(c0 + lr) * HDIM + lk;

    int tx = tid & 15, ty = tid >> 4;
    float acc1[4][4] = {{0}}, acc3[4][4] = {{0}};

    // register prefetch (single smem buffer, hides global latency)
    float4 xa = *(const float4*)xp;
    float4 ba = *(const float4*)b1p;
    float4 bc = *(const float4*)b3p;

    for (int k0 = 0; k0 < HDIM; k0 += BK) {
        Xs [lk+0][lr] = xa.x; Xs [lk+1][lr] = xa.y; Xs [lk+2][lr] = xa.z; Xs [lk+3][lr] = xa.w;
        B1s[lk+0][lr] = ba.x; B1s[lk+1][lr] = ba.y; B1s[lk+2][lr] = ba.z; B1s[lk+3][lr] = ba.w;
        B3s[lk+0][lr] = bc.x; B3s[lk+1][lr] = bc.y; B3s[lk+2][lr] = bc.z; B3s[lk+3][lr] = bc.w;
        __syncthreads();

        if (k0 + BK < HDIM) {
            xa = *(const float4*)(xp  + k0 + BK);
            ba = *(const float4*)(b1p + k0 + BK);
            bc = *(const float4*)(b3p + k0 + BK);
        }

#pragma unroll
        for (int kk = 0; kk < BK; kk++) {
            float4 av  = *(const float4*)&Xs [kk][ty << 2];
            float4 b1v = *(const float4*)&B1s[kk][tx << 2];
            float4 b3v = *(const float4*)&B3s[kk][tx << 2];
            float ar[4]  = {av.x,  av.y,  av.z,  av.w};
            float b1r[4] = {b1v.x, b1v.y, b1v.z, b1v.w};
            float b3r[4] = {b3v.x, b3v.y, b3v.z, b3v.w};
#pragma unroll
            for (int i = 0; i < 4; i++)
#pragma unroll
                for (int j = 0; j < 4; j++) {
                    acc1[i][j] += ar[i] * b1r[j];
                    acc3[i][j] += ar[i] * b3r[j];
                }
        }
        __syncthreads();
    }

    int row = ty << 2, col = tx << 2;
#pragma unroll
    for (int i = 0; i < 4; i++) {
        int rr = r0 + row + i;
        if (rr >= cnt) continue;
        float* hp = g_h + ((size_t)e * TMAX + rr) * FDIM + c0 + col;
#pragma unroll
        for (int j = 0; j < 4; j++) {
            float g = acc1[i][j];
            hp[j] = (g / (1.f + expf(-g))) * acc3[i][j];   // silu(g)*v
        }
    }
}

// -------- stage 2: out[tok] += wt * (h @ W2^T), grouped by expert --------
__global__ void __launch_bounds__(256)
k_ffn2(const float* __restrict__ w2, float* __restrict__ out) {
    int e   = blockIdx.z;
    int cnt = g_count[e];
    int r0  = blockIdx.y * BM;
    if (r0 >= cnt) return;
    int c0  = blockIdx.x * BM;                   // over HDIM (32 tiles)

    __shared__ __align__(16) float As[BK][PAD];
    __shared__ __align__(16) float Bs[BK][PAD];
    __shared__ int   toks[BM];
    __shared__ float wts[BM];

    int tid = threadIdx.x;
    if (tid < BM) {
        int rr = r0 + tid;
        int v  = (rr < cnt) ? rr : 0;
        toks[tid] = g_tok[e * TMAX + v];
        wts[tid]  = g_wt[e * TMAX + v];
    }
    __syncthreads();

    int lr = tid >> 2;
    int lk = (tid & 3) << 2;

    // rows >= cnt read zero/stale rows of g_h; their accs are discarded below
    const float* ap = g_h + ((size_t)e * TMAX + r0 + lr) * FDIM + lk;
    const float* bp = w2  + (size_t)e * HDIM * FDIM + (size_t)(c0 + lr) * FDIM + lk;

    int tx = tid & 15, ty = tid >> 4;
    float acc[4][4] = {{0}};

    float4 aa = *(const float4*)ap;
    float4 bb = *(const float4*)bp;

    for (int k0 = 0; k0 < FDIM; k0 += BK) {
        As[lk+0][lr] = aa.x; As[lk+1][lr] = aa.y; As[lk+2][lr] = aa.z; As[lk+3][lr] = aa.w;
        Bs[lk+0][lr] = bb.x; Bs[lk+1][lr] = bb.y; Bs[lk+2][lr] = bb.z; Bs[lk+3][lr] = bb.w;
        __syncthreads();

        if (k0 + BK < FDIM) {
            aa = *(const float4*)(ap + k0 + BK);
            bb = *(const float4*)(bp + k0 + BK);
        }

#pragma unroll
        for (int kk = 0; kk < BK; kk++) {
            float4 av = *(const float4*)&As[kk][ty << 2];
            float4 bv = *(const float4*)&Bs[kk][tx << 2];
            float ar[4] = {av.x, av.y, av.z, av.w};
            float br[4] = {bv.x, bv.y, bv.z, bv.w};
#pragma unroll
            for (int i = 0; i < 4; i++)
#pragma unroll
                for (int j = 0; j < 4; j++)
                    acc[i][j] += ar[i] * br[j];
        }
        __syncthreads();
    }

    int row = ty << 2, col = tx << 2;
#pragma unroll
    for (int i = 0; i < 4; i++) {
        int rr = r0 + row + i;
        if (rr >= cnt) continue;
        int   tok = toks[row + i];
        float wt  = wts[row + i];
        float* op = out + (size_t)tok * HDIM + c0 + col;
#pragma unroll
        for (int j = 0; j < 4; j++)
            atomicAdd(&op[j], acc[i][j] * wt);   // exactly 2 adds/element, no contention
    }
}

extern "C" void kernel_launch(void* const* d_in, const int* in_sizes, int n_in,
                              void* d_out, int out_size) {
    const float* x  = (const float*)d_in[0];   // hidden_states [4,1024,2048]
    const float* gw = (const float*)d_in[1];   // gate_w [12,2048]
    const float* w1 = (const float*)d_in[2];   // [12,1280,2048]
    const float* w2 = (const float*)d_in[3];   // [12,2048,1280]
    const float* w3 = (const float*)d_in[4];   // [12,1280,2048]
    float* out = (float*)d_out;

    cudaMemsetAsync(out, 0, (size_t)out_size * sizeof(float));
    k_zero<<<1, 32>>>();
    k_gate<<<TMAX, 128>>>(x, gw);
    k_ffn1<<<dim3(FDIM / BM, TMAX / BM, NE), 256>>>(x, w1, w3);
    k_ffn2<<<dim3(HDIM / BM, TMAX / BM, NE), 256>>>(w2, out);
}

// round 12
// speedup vs baseline: 1.9134x; 1.9134x over previous
#include <cuda_runtime.h>
#include <cuda_bf16.h>
#include <cstdint>
#include <math.h>

#define NE   12
#define HDIM 2048
#define FDIM 1280
#define TMAX 4096
#define TSTR 40                      // smem row stride in bf16 (80 B): conflict-free ldmatrix
#define TILE_B (128 * TSTR * 2)      // 10240 B per tile
#define BUF_B  (4 * TILE_B)          // Ah, Al, Bh, Bl
#define SMEM_SZ (2 * BUF_B + 512)    // two buffers + toks

// ---------------- device scratch ----------------
__device__ int   g_count[NE];
__device__ int   g_tok[NE * TMAX];
__device__ int   g_cslot[2 * TMAX];
__device__ float g_cw[2 * TMAX];
__device__ float g_a1[(size_t)NE * TMAX * FDIM];  // raw x@w1^T
__device__ float g_h [(size_t)NE * TMAX * FDIM];  // silu(a1)*a3
__device__ float g_o [(size_t)NE * TMAX * HDIM];  // per-slot outputs

__device__ __forceinline__ uint32_t smem_u32(const void* p) {
    uint32_t a;
    asm("{ .reg .u64 t; cvta.to.shared.u64 t, %1; cvt.u32.u64 %0, t; }" : "=r"(a) : "l"(p));
    return a;
}

#define LDM4(r, addr) \
    asm volatile("ldmatrix.sync.aligned.m8n8.x4.shared.b16 {%0,%1,%2,%3}, [%4];" \
        : "=r"((r)[0]), "=r"((r)[1]), "=r"((r)[2]), "=r"((r)[3]) : "r"(addr))

#define MMA(d, a, b) \
    asm volatile("mma.sync.aligned.m16n8k16.row.col.f32.bf16.bf16.f32 " \
        "{%0,%1,%2,%3}, {%4,%5,%6,%7}, {%8,%9}, {%0,%1,%2,%3};" \
        : "+f"((d)[0]), "+f"((d)[1]), "+f"((d)[2]), "+f"((d)[3]) \
        : "r"((a)[0]), "r"((a)[1]), "r"((a)[2]), "r"((a)[3]), "r"((b)[0]), "r"((b)[1]))

// float4 -> 4 bf16 hi (uint2) + 4 bf16 lo (uint2)
__device__ __forceinline__ void cvt4(float4 f, uint2& H, uint2& L) {
    __nv_bfloat16 h0 = __float2bfloat16_rn(f.x), h1 = __float2bfloat16_rn(f.y);
    __nv_bfloat16 h2 = __float2bfloat16_rn(f.z), h3 = __float2bfloat16_rn(f.w);
    __nv_bfloat16 l0 = __float2bfloat16_rn(f.x - __bfloat162float(h0));
    __nv_bfloat16 l1 = __float2bfloat16_rn(f.y - __bfloat162float(h1));
    __nv_bfloat16 l2 = __float2bfloat16_rn(f.z - __bfloat162float(h2));
    __nv_bfloat16 l3 = __float2bfloat16_rn(f.w - __bfloat162float(h3));
    H.x = (uint32_t)__bfloat16_as_ushort(h0) | ((uint32_t)__bfloat16_as_ushort(h1) << 16);
    H.y = (uint32_t)__bfloat16_as_ushort(h2) | ((uint32_t)__bfloat16_as_ushort(h3) << 16);
    L.x = (uint32_t)__bfloat16_as_ushort(l0) | ((uint32_t)__bfloat16_as_ushort(l1) << 16);
    L.y = (uint32_t)__bfloat16_as_ushort(l2) | ((uint32_t)__bfloat16_as_ushort(l3) << 16);
}

// ---------------- routing ----------------
__global__ void k_zero() { if (threadIdx.x < NE) g_count[threadIdx.x] = 0; }

__global__ void k_gate(const float* __restrict__ x, const float* __restrict__ gw) {
    int t = blockIdx.x, tid = threadIdx.x;
    const float* xr = x + (size_t)t * HDIM;
    float acc[NE];
#pragma unroll
    for (int e = 0; e < NE; e++) acc[e] = 0.f;
    for (int k = tid; k < HDIM; k += 128) {
        float xv = xr[k];
#pragma unroll
        for (int e = 0; e < NE; e++) acc[e] += xv * gw[e * HDIM + k];
    }
    __shared__ float s[NE][128];
#pragma unroll
    for (int e = 0; e < NE; e++) s[e][tid] = acc[e];
    __syncthreads();
    if (tid < NE) {
        float v = 0.f;
        for (int i = 0; i < 128; i++) v += s[tid][i];
        s[tid][0] = v;
    }
    __syncthreads();
    if (tid == 0) {
        float l[NE];
#pragma unroll
        for (int e = 0; e < NE; e++) l[e] = s[e][0];
        int i0 = 0;
#pragma unroll
        for (int e = 1; e < NE; e++) if (l[e] > l[i0]) i0 = e;
        int i1 = (i0 == 0) ? 1 : 0;
#pragma unroll
        for (int e = 0; e < NE; e++) if (e != i0 && l[e] > l[i1]) i1 = e;
        float w0 = 1.f / (1.f + expf(l[i1] - l[i0]));
        float w1 = 1.f - w0;
        int p0 = atomicAdd(&g_count[i0], 1);
        g_tok[i0 * TMAX + p0] = t;
        g_cslot[2 * t] = i0 * TMAX + p0;      g_cw[2 * t] = w0;
        int p1 = atomicAdd(&g_count[i1], 1);
        g_tok[i1 * TMAX + p1] = t;
        g_cslot[2 * t + 1] = i1 * TMAX + p1;  g_cw[2 * t + 1] = w1;
    }
}

// ---------------- grouped GEMM via mma.sync, bf16 hi/lo split ----------------
// OP 0: g_a1 = X@W1^T      (A gathered, K=2048, N=1280)
// OP 1: g_h  = silu(g_a1) * (X@W3^T)
// OP 2: g_o  = g_h@W2^T    (A contiguous, K=1280, N=2048)
template <int OP>
__global__ void __launch_bounds__(256)
k_gemm(const float* __restrict__ A0, const float* __restrict__ W) {
    constexpr int KD  = (OP == 2) ? FDIM : HDIM;
    constexpr int NW  = (OP == 2) ? HDIM : FDIM;
    constexpr int NIT = KD / 32;

    int e = blockIdx.z, cnt = g_count[e];
    int r0 = blockIdx.y * 128;
    if (r0 >= cnt) return;
    int c0 = blockIdx.x * 128;

    extern __shared__ char sm[];
    uint32_t sb = smem_u32(sm);
    int tid = threadIdx.x, lane = tid & 31, wid = tid >> 5;
    int wm = wid >> 2, wn = wid & 3;       // 2x4 warp grid

    int* toks = (int*)(sm + 2 * BUF_B);
    if (OP != 2) {
        if (tid < 128) {
            int p = r0 + tid;
            toks[tid] = g_tok[e * TMAX + (p < cnt ? p : cnt - 1)];
        }
        __syncthreads();
    }

    int lrow = tid >> 3;                   // 0..31
    int lcol = (tid & 7) << 2;             // 0..28
    const float* ap[4];
    const float* bp[4];
#pragma unroll
    for (int i = 0; i < 4; i++) {
        int r = lrow + 32 * i;
        if (OP == 2) ap[i] = A0 + ((size_t)e * TMAX + r0 + r) * FDIM + lcol;
        else         ap[i] = A0 + (size_t)toks[r] * HDIM + lcol;
        bp[i] = W + ((size_t)e * NW + c0 + r) * KD + lcol;
    }

    float4 ar[4], br[4];
    float acc[4][4][4];
#pragma unroll
    for (int a = 0; a < 4; a++)
#pragma unroll
        for (int b = 0; b < 4; b++)
#pragma unroll
            for (int c = 0; c < 4; c++) acc[a][b][c] = 0.f;

    auto LOAD = [&](int it) {
#pragma unroll
        for (int i = 0; i < 4; i++) {
            ar[i] = *(const float4*)(ap[i] + it * 32);
            br[i] = *(const float4*)(bp[i] + it * 32);
        }
    };
    auto STORE = [&](int buf) {
        char* base = sm + buf * BUF_B;
#pragma unroll
        for (int i = 0; i < 4; i++) {
            uint32_t off = ((lrow + 32 * i) * TSTR + lcol) * 2;
            uint2 H, L;
            cvt4(ar[i], H, L);
            *(uint2*)(base + off)              = H;   // Ah
            *(uint2*)(base + TILE_B + off)     = L;   // Al
            cvt4(br[i], H, L);
            *(uint2*)(base + 2 * TILE_B + off) = H;   // Bh
            *(uint2*)(base + 3 * TILE_B + off) = L;   // Bl
        }
    };
    auto COMPUTE = [&](int buf) {
        uint32_t base = sb + buf * BUF_B;
#pragma unroll
        for (int ks = 0; ks < 2; ks++) {
            uint32_t Ah[4][4], Al[4][4], Bh[4][2], Bl[4][2];
            uint32_t la = ((lane & 15) * TSTR + ((lane >> 4) << 3) + ks * 16) * 2;
#pragma unroll
            for (int mf = 0; mf < 4; mf++) {
                uint32_t ad = base + (wm * 64 + mf * 16) * (TSTR * 2) + la;
                LDM4(Ah[mf], ad);
                LDM4(Al[mf], ad + TILE_B);
            }
            uint32_t lb = (((lane & 7) + ((lane >> 4) << 3)) * TSTR
                           + ks * 16 + ((lane >> 3) & 1) * 8) * 2;
#pragma unroll
            for (int nf2 = 0; nf2 < 2; nf2++) {
                uint32_t bd = base + 2 * TILE_B + (wn * 32 + nf2 * 16) * (TSTR * 2) + lb;
                uint32_t t[4];
                LDM4(t, bd);
                Bh[2 * nf2][0] = t[0]; Bh[2 * nf2][1] = t[1];
                Bh[2 * nf2 + 1][0] = t[2]; Bh[2 * nf2 + 1][1] = t[3];
                LDM4(t, bd + TILE_B);
                Bl[2 * nf2][0] = t[0]; Bl[2 * nf2][1] = t[1];
                Bl[2 * nf2 + 1][0] = t[2]; Bl[2 * nf2 + 1][1] = t[3];
            }
#pragma unroll
            for (int mf = 0; mf < 4; mf++)
#pragma unroll
                for (int nf = 0; nf < 4; nf++) {
                    MMA(acc[mf][nf], Ah[mf], Bh[nf]);
                    MMA(acc[mf][nf], Ah[mf], Bl[nf]);
                    MMA(acc[mf][nf], Al[mf], Bh[nf]);
                }
        }
    };

    // 2-stage pipeline: store(it+1) from prefetched regs, issue load(it+2), compute(it)
    LOAD(0);
    STORE(0);
    if (NIT > 1) LOAD(1);
    __syncthreads();
    for (int it = 0; it < NIT; it++) {
        if (it + 1 < NIT) STORE((it + 1) & 1);
        if (it + 2 < NIT) LOAD(it + 2);
        COMPUTE(it & 1);
        __syncthreads();
    }

    // ---------------- epilogue ----------------
    int rb = r0 + wm * 64;
    int cb = c0 + wn * 32 + (lane & 3) * 2;
#pragma unroll
    for (int mf = 0; mf < 4; mf++) {
#pragma unroll
        for (int h = 0; h < 2; h++) {
            int row = rb + mf * 16 + (lane >> 2) + 8 * h;
            if (row >= cnt) continue;
            size_t rowbase = ((size_t)e * TMAX + row) * (size_t)NW;
#pragma unroll
            for (int nf = 0; nf < 4; nf++) {
                size_t idx = rowbase + (cb + nf * 8);
                float2 v = make_float2(acc[mf][nf][2 * h], acc[mf][nf][2 * h + 1]);
                if (OP == 0) {
                    *(float2*)&g_a1[idx] = v;
                } else if (OP == 1) {
                    float2 a1 = *(const float2*)&g_a1[idx];
                    float2 o;
                    o.x = v.x * a1.x / (1.f + __expf(-a1.x));
                    o.y = v.y * a1.y / (1.f + __expf(-a1.y));
                    *(float2*)&g_h[idx] = o;
                } else {
                    *(float2*)&g_o[idx] = v;
                }
            }
        }
    }
}

// ---------------- combine: out[t] = w0*g_o[slot0] + w1*g_o[slot1] ----------------
__global__ void __launch_bounds__(256) k_comb(float* __restrict__ out) {
    int i  = blockIdx.x * 256 + threadIdx.x;
    int t  = i >> 9;                       // HDIM/4 = 512 float4 per token
    int c4 = (i & 511) << 2;
    int   s0 = g_cslot[2 * t],  s1 = g_cslot[2 * t + 1];
    float w0 = g_cw[2 * t],     w1 = g_cw[2 * t + 1];
    float4 a = *(const float4*)(g_o + (size_t)s0 * HDIM + c4);
    float4 b = *(const float4*)(g_o + (size_t)s1 * HDIM + c4);
    float4 o;
    o.x = w0 * a.x + w1 * b.x;  o.y = w0 * a.y + w1 * b.y;
    o.z = w0 * a.z + w1 * b.z;  o.w = w0 * a.w + w1 * b.w;
    *(float4*)(out + (size_t)t * HDIM + c4) = o;
}

// ---------------- host ----------------
extern "C" void kernel_launch(void* const* d_in, const int* in_sizes, int n_in,
                              void* d_out, int out_size) {
    const float* x  = (const float*)d_in[0];
    const float* gw = (const float*)d_in[1];
    const float* w1 = (const float*)d_in[2];
    const float* w2 = (const float*)d_in[3];
    const float* w3 = (const float*)d_in[4];
    float* out = (float*)d_out;

    cudaFuncSetAttribute(k_gemm<0>, cudaFuncAttributeMaxDynamicSharedMemorySize, SMEM_SZ);
    cudaFuncSetAttribute(k_gemm<1>, cudaFuncAttributeMaxDynamicSharedMemorySize, SMEM_SZ);
    cudaFuncSetAttribute(k_gemm<2>, cudaFuncAttributeMaxDynamicSharedMemorySize, SMEM_SZ);

    float* g_h_ptr;
    cudaGetSymbolAddress((void**)&g_h_ptr, g_h);

    k_zero<<<1, 32>>>();
    k_gate<<<TMAX, 128>>>(x, gw);
    k_gemm<0><<<dim3(FDIM / 128, TMAX / 128, NE), 256, SMEM_SZ>>>(x, w1);
    k_gemm<1><<<dim3(FDIM / 128, TMAX / 128, NE), 256, SMEM_SZ>>>(x, w3);
    k_gemm<2><<<dim3(HDIM / 128, TMAX / 128, NE), 256, SMEM_SZ>>>(g_h_ptr, w2);
    k_comb<<<TMAX * (HDIM / 4) / 256, 256>>>(out);
}

// round 13
// speedup vs baseline: 1.9769x; 1.0332x over previous
#include <cuda_runtime.h>
#include <cuda_bf16.h>
#include <cstdint>
#include <math.h>

#define NE   12
#define HDIM 2048
#define FDIM 1280
#define TMAX 4096
#define TSTR 40                       // smem row stride in bf16 (80B), conflict-free
#define KC   32                       // k per stage
#define NSTG 3
#define AST  (128 * TSTR * 2)         // 10240 B per array per stage
#define STG_B (4 * AST)               // Ah, Al, Bh, Bl
#define SMEM_SZ (NSTG * STG_B + 512)

// ---------------- device scratch ----------------
__device__ int   g_count[NE];
__device__ int   g_tok[NE * TMAX];
__device__ int   g_cslot[2 * TMAX];
__device__ float g_cw[2 * TMAX];
__device__ __nv_bfloat16 g_xh [(size_t)TMAX * HDIM],     g_xl [(size_t)TMAX * HDIM];
__device__ __nv_bfloat16 g_w1h[(size_t)NE * FDIM * HDIM], g_w1l[(size_t)NE * FDIM * HDIM];
__device__ __nv_bfloat16 g_w3h[(size_t)NE * FDIM * HDIM], g_w3l[(size_t)NE * FDIM * HDIM];
__device__ __nv_bfloat16 g_w2h[(size_t)NE * HDIM * FDIM], g_w2l[(size_t)NE * HDIM * FDIM];
__device__ float g_a1[(size_t)NE * TMAX * FDIM];
__device__ __nv_bfloat16 g_hh [(size_t)NE * TMAX * FDIM], g_hl [(size_t)NE * TMAX * FDIM];
__device__ float g_o [(size_t)NE * TMAX * HDIM];

__device__ __forceinline__ uint32_t smem_u32(const void* p) {
    uint32_t a;
    asm("{ .reg .u64 t; cvta.to.shared.u64 t, %1; cvt.u32.u64 %0, t; }" : "=r"(a) : "l"(p));
    return a;
}

#define LDM4(r, addr) \
    asm volatile("ldmatrix.sync.aligned.m8n8.x4.shared.b16 {%0,%1,%2,%3}, [%4];" \
        : "=r"((r)[0]), "=r"((r)[1]), "=r"((r)[2]), "=r"((r)[3]) : "r"(addr))

#define MMA(d, a, b) \
    asm volatile("mma.sync.aligned.m16n8k16.row.col.f32.bf16.bf16.f32 " \
        "{%0,%1,%2,%3}, {%4,%5,%6,%7}, {%8,%9}, {%0,%1,%2,%3};" \
        : "+f"((d)[0]), "+f"((d)[1]), "+f"((d)[2]), "+f"((d)[3]) \
        : "r"((a)[0]), "r"((a)[1]), "r"((a)[2]), "r"((a)[3]), "r"((b)[0]), "r"((b)[1]))

#define CP_ASYNC(dst, src) \
    asm volatile("cp.async.cg.shared.global [%0], [%1], 16;" :: "r"(dst), "l"(src))
#define CP_COMMIT() asm volatile("cp.async.commit_group;")
#define CP_WAIT1()  asm volatile("cp.async.wait_group 1;")

__device__ __forceinline__ uint16_t bfu(__nv_bfloat16 b) { return __bfloat16_as_ushort(b); }

// ---------------- fp32 -> bf16 hi/lo conversion ----------------
__global__ void __launch_bounds__(256) k_cvt(const float4* __restrict__ s,
                                             uint2* __restrict__ hi, uint2* __restrict__ lo,
                                             int n4) {
    int i = blockIdx.x * 256 + threadIdx.x;
    if (i >= n4) return;
    float4 f = s[i];
    __nv_bfloat16 h0 = __float2bfloat16_rn(f.x), h1 = __float2bfloat16_rn(f.y);
    __nv_bfloat16 h2 = __float2bfloat16_rn(f.z), h3 = __float2bfloat16_rn(f.w);
    __nv_bfloat16 l0 = __float2bfloat16_rn(f.x - __bfloat162float(h0));
    __nv_bfloat16 l1 = __float2bfloat16_rn(f.y - __bfloat162float(h1));
    __nv_bfloat16 l2 = __float2bfloat16_rn(f.z - __bfloat162float(h2));
    __nv_bfloat16 l3 = __float2bfloat16_rn(f.w - __bfloat162float(h3));
    uint2 H, L;
    H.x = (uint32_t)bfu(h0) | ((uint32_t)bfu(h1) << 16);
    H.y = (uint32_t)bfu(h2) | ((uint32_t)bfu(h3) << 16);
    L.x = (uint32_t)bfu(l0) | ((uint32_t)bfu(l1) << 16);
    L.y = (uint32_t)bfu(l2) | ((uint32_t)bfu(l3) << 16);
    hi[i] = H;  lo[i] = L;
}

// ---------------- routing ----------------
__global__ void k_zero() { if (threadIdx.x < NE) g_count[threadIdx.x] = 0; }

__global__ void k_gate(const float* __restrict__ x, const float* __restrict__ gw) {
    int t = blockIdx.x, tid = threadIdx.x;
    const float* xr = x + (size_t)t * HDIM;
    float acc[NE];
#pragma unroll
    for (int e = 0; e < NE; e++) acc[e] = 0.f;
    for (int k = tid; k < HDIM; k += 128) {
        float xv = xr[k];
#pragma unroll
        for (int e = 0; e < NE; e++) acc[e] += xv * gw[e * HDIM + k];
    }
    __shared__ float s[NE][128];
#pragma unroll
    for (int e = 0; e < NE; e++) s[e][tid] = acc[e];
    __syncthreads();
    if (tid < NE) {
        float v = 0.f;
        for (int i = 0; i < 128; i++) v += s[tid][i];
        s[tid][0] = v;
    }
    __syncthreads();
    if (tid == 0) {
        float l[NE];
#pragma unroll
        for (int e = 0; e < NE; e++) l[e] = s[e][0];
        int i0 = 0;
#pragma unroll
        for (int e = 1; e < NE; e++) if (l[e] > l[i0]) i0 = e;
        int i1 = (i0 == 0) ? 1 : 0;
#pragma unroll
        for (int e = 0; e < NE; e++) if (e != i0 && l[e] > l[i1]) i1 = e;
        float w0 = 1.f / (1.f + expf(l[i1] - l[i0]));
        float w1 = 1.f - w0;
        int p0 = atomicAdd(&g_count[i0], 1);
        g_tok[i0 * TMAX + p0] = t;
        g_cslot[2 * t] = i0 * TMAX + p0;      g_cw[2 * t] = w0;
        int p1 = atomicAdd(&g_count[i1], 1);
        g_tok[i1 * TMAX + p1] = t;
        g_cslot[2 * t + 1] = i1 * TMAX + p1;  g_cw[2 * t + 1] = w1;
    }
}

// ---------------- grouped GEMM: cp.async 3-stage + mma.sync bf16 hi/lo ----------------
// OP 0: g_a1 = X@W1^T          OP 1: g_h = silu(g_a1)*(X@W3^T)     OP 2: g_o = h@W2^T
template <int OP>
__global__ void __launch_bounds__(256)
k_gemm() {
    constexpr int KD  = (OP == 2) ? FDIM : HDIM;
    constexpr int NW  = (OP == 2) ? HDIM : FDIM;
    constexpr int NIT = KD / KC;

    int e = blockIdx.z, cnt = g_count[e];
    int r0 = blockIdx.y * 128;
    if (r0 >= cnt) return;
    int c0 = blockIdx.x * 128;

    extern __shared__ char sm[];
    uint32_t sb = smem_u32(sm);
    int tid = threadIdx.x, lane = tid & 31, wid = tid >> 5;
    int wm = wid >> 2, wn = wid & 3;

    int* toks = (int*)(sm + NSTG * STG_B);
    if (OP != 2) {
        if (tid < 128) {
            int p = r0 + tid;
            toks[tid] = g_tok[e * TMAX + (p < cnt ? p : cnt - 1)];
        }
        __syncthreads();
    }

    // per-thread cp.async assignment: 8 x 16B chunks per stage
    uint32_t dsto[8];
    const char* srcp[8];
#pragma unroll
    for (int j = 0; j < 8; j++) {
        int g   = tid + 256 * j;
        int arr = g >> 9;           // 0=Ah 1=Al 2=Bh 3=Bl
        int idx = g & 511;
        int row = idx >> 2;
        int ch  = idx & 3;
        dsto[j] = (uint32_t)(arr * AST + row * (TSTR * 2) + ch * 16);
        const __nv_bfloat16* base;
        size_t roff;
        if (arr < 2) {
            if (OP == 2) { base = (arr == 0) ? g_hh : g_hl; roff = ((size_t)e * TMAX + r0 + row) * KD; }
            else         { base = (arr == 0) ? g_xh : g_xl; roff = (size_t)toks[row] * KD; }
        } else {
            if (OP == 0)      base = (arr == 2) ? g_w1h : g_w1l;
            else if (OP == 1) base = (arr == 2) ? g_w3h : g_w3l;
            else              base = (arr == 2) ? g_w2h : g_w2l;
            roff = ((size_t)e * NW + c0 + row) * KD;
        }
        srcp[j] = (const char*)(base + roff) + ch * 16;
    }

    float acc[4][4][4];
#pragma unroll
    for (int a = 0; a < 4; a++)
#pragma unroll
        for (int b = 0; b < 4; b++)
#pragma unroll
            for (int c = 0; c < 4; c++) acc[a][b][c] = 0.f;

    auto ISSUE = [&](int slot) {
        uint32_t dbase = sb + (uint32_t)slot * STG_B;
#pragma unroll
        for (int j = 0; j < 8; j++) {
            CP_ASYNC(dbase + dsto[j], srcp[j]);
            srcp[j] += KC * 2;      // advance 64B along K
        }
        CP_COMMIT();
    };

    auto COMPUTE = [&](int slot) {
        uint32_t base = sb + (uint32_t)slot * STG_B;
#pragma unroll
        for (int ks = 0; ks < 2; ks++) {
            uint32_t Ah[4][4], Al[4][4], Bh[4][2], Bl[4][2];
            uint32_t la = ((lane & 15) * TSTR + ((lane >> 4) << 3) + ks * 16) * 2;
#pragma unroll
            for (int mf = 0; mf < 4; mf++) {
                uint32_t ad = base + (wm * 64 + mf * 16) * (TSTR * 2) + la;
                LDM4(Ah[mf], ad);
                LDM4(Al[mf], ad + AST);
            }
            uint32_t lb = (((lane & 7) + ((lane >> 4) << 3)) * TSTR
                           + ks * 16 + ((lane >> 3) & 1) * 8) * 2;
#pragma unroll
            for (int nf2 = 0; nf2 < 2; nf2++) {
                uint32_t bd = base + 2 * AST + (wn * 32 + nf2 * 16) * (TSTR * 2) + lb;
                uint32_t t[4];
                LDM4(t, bd);
                Bh[2 * nf2][0] = t[0]; Bh[2 * nf2][1] = t[1];
                Bh[2 * nf2 + 1][0] = t[2]; Bh[2 * nf2 + 1][1] = t[3];
                LDM4(t, bd + AST);
                Bl[2 * nf2][0] = t[0]; Bl[2 * nf2][1] = t[1];
                Bl[2 * nf2 + 1][0] = t[2]; Bl[2 * nf2 + 1][1] = t[3];
            }
#pragma unroll
            for (int mf = 0; mf < 4; mf++)
#pragma unroll
                for (int nf = 0; nf < 4; nf++) {
                    MMA(acc[mf][nf], Ah[mf], Bh[nf]);
                    MMA(acc[mf][nf], Ah[mf], Bl[nf]);
                    MMA(acc[mf][nf], Al[mf], Bh[nf]);
                }
        }
    };

    ISSUE(0);
    ISSUE(1);
    for (int it = 0; it < NIT; it++) {
        CP_WAIT1();                 // stage `it` landed (<=1 group outstanding)
        __syncthreads();            // all threads' data visible; prev compute done
        if (it + 2 < NIT) ISSUE((it + 2) % NSTG);
        COMPUTE(it % NSTG);
    }

    // ---------------- epilogue ----------------
    int rb = r0 + wm * 64;
    int cb = c0 + wn * 32 + (lane & 3) * 2;
#pragma unroll
    for (int mf = 0; mf < 4; mf++) {
#pragma unroll
        for (int h = 0; h < 2; h++) {
            int row = rb + mf * 16 + (lane >> 2) + 8 * h;
            if (row >= cnt) continue;
            size_t rowbase = ((size_t)e * TMAX + row) * (size_t)NW;
#pragma unroll
            for (int nf = 0; nf < 4; nf++) {
                size_t idx = rowbase + (cb + nf * 8);
                float vx = acc[mf][nf][2 * h], vy = acc[mf][nf][2 * h + 1];
                if (OP == 0) {
                    *(float2*)&g_a1[idx] = make_float2(vx, vy);
                } else if (OP == 1) {
                    float2 a1 = *(const float2*)&g_a1[idx];
                    float ox = vx * a1.x / (1.f + __expf(-a1.x));
                    float oy = vy * a1.y / (1.f + __expf(-a1.y));
                    __nv_bfloat16 hx = __float2bfloat16_rn(ox), hy = __float2bfloat16_rn(oy);
                    __nv_bfloat16 lx = __float2bfloat16_rn(ox - __bfloat162float(hx));
                    __nv_bfloat16 ly = __float2bfloat16_rn(oy - __bfloat162float(hy));
                    *(uint32_t*)&g_hh[idx] = (uint32_t)bfu(hx) | ((uint32_t)bfu(hy) << 16);
                    *(uint32_t*)&g_hl[idx] = (uint32_t)bfu(lx) | ((uint32_t)bfu(ly) << 16);
                } else {
                    *(float2*)&g_o[idx] = make_float2(vx, vy);
                }
            }
        }
    }
}

// ---------------- combine ----------------
__global__ void __launch_bounds__(256) k_comb(float* __restrict__ out) {
    int i  = blockIdx.x * 256 + threadIdx.x;
    int t  = i >> 9;
    int c4 = (i & 511) << 2;
    int   s0 = g_cslot[2 * t],  s1 = g_cslot[2 * t + 1];
    float w0 = g_cw[2 * t],     w1 = g_cw[2 * t + 1];
    float4 a = *(const float4*)(g_o + (size_t)s0 * HDIM + c4);
    float4 b = *(const float4*)(g_o + (size_t)s1 * HDIM + c4);
    float4 o;
    o.x = w0 * a.x + w1 * b.x;  o.y = w0 * a.y + w1 * b.y;
    o.z = w0 * a.z + w1 * b.z;  o.w = w0 * a.w + w1 * b.w;
    *(float4*)(out + (size_t)t * HDIM + c4) = o;
}

// ---------------- host ----------------
extern "C" void kernel_launch(void* const* d_in, const int* in_sizes, int n_in,
                              void* d_out, int out_size) {
    const float* x  = (const float*)d_in[0];
    const float* gw = (const float*)d_in[1];
    const float* w1 = (const float*)d_in[2];
    const float* w2 = (const float*)d_in[3];
    const float* w3 = (const float*)d_in[4];
    float* out = (float*)d_out;

    cudaFuncSetAttribute(k_gemm<0>, cudaFuncAttributeMaxDynamicSharedMemorySize, SMEM_SZ);
    cudaFuncSetAttribute(k_gemm<1>, cudaFuncAttributeMaxDynamicSharedMemorySize, SMEM_SZ);
    cudaFuncSetAttribute(k_gemm<2>, cudaFuncAttributeMaxDynamicSharedMemorySize, SMEM_SZ);

    void *xh, *xl, *w1h, *w1l, *w3h, *w3l, *w2h, *w2l;
    cudaGetSymbolAddress(&xh,  g_xh);  cudaGetSymbolAddress(&xl,  g_xl);
    cudaGetSymbolAddress(&w1h, g_w1h); cudaGetSymbolAddress(&w1l, g_w1l);
    cudaGetSymbolAddress(&w3h, g_w3h); cudaGetSymbolAddress(&w3l, g_w3l);
    cudaGetSymbolAddress(&w2h, g_w2h); cudaGetSymbolAddress(&w2l, g_w2l);

    const int nx4 = TMAX * HDIM / 4;
    const int nw4 = NE * FDIM * HDIM / 4;   // same count for w2

    k_zero<<<1, 32>>>();
    k_gate<<<TMAX, 128>>>(x, gw);
    k_cvt<<<(nx4 + 255) / 256, 256>>>((const float4*)x,  (uint2*)xh,  (uint2*)xl,  nx4);
    k_cvt<<<(nw4 + 255) / 256, 256>>>((const float4*)w1, (uint2*)w1h, (uint2*)w1l, nw4);
    k_cvt<<<(nw4 + 255) / 256, 256>>>((const float4*)w3, (uint2*)w3h, (uint2*)w3l, nw4);
    k_cvt<<<(nw4 + 255) / 256, 256>>>((const float4*)w2, (uint2*)w2h, (uint2*)w2l, nw4);
    k_gemm<0><<<dim3(FDIM / 128, TMAX / 128, NE), 256, SMEM_SZ>>>();
    k_gemm<1><<<dim3(FDIM / 128, TMAX / 128, NE), 256, SMEM_SZ>>>();
    k_gemm<2><<<dim3(HDIM / 128, TMAX / 128, NE), 256, SMEM_SZ>>>();
    k_comb<<<TMAX * (HDIM / 4) / 256, 256>>>(out);
}

// round 15
// speedup vs baseline: 2.2958x; 1.1613x over previous
#include <cuda_runtime.h>
#include <cuda_bf16.h>
#include <cstdint>
#include <math.h>

#define NE   12
#define HDIM 2048
#define FDIM 1280
#define TMAX 4096
#define TSTR 40                       // smem row stride in bf16 (80B), conflict-free
#define KC   32                       // k per stage
#define NSTG 2
#define AST  (128 * TSTR * 2)         // 10240 B per array per stage
#define STG_B (4 * AST)               // Ah, Al, Bh, Bl
#define SMEM_SZ (NSTG * STG_B + 512)  // 82432 B -> 2 CTAs/SM

// ---------------- device scratch ----------------
__device__ int   g_count[NE];
__device__ int   g_tok[NE * TMAX];
__device__ int   g_cslot[2 * TMAX];
__device__ float g_cw[2 * TMAX];
__device__ __nv_bfloat16 g_xh [(size_t)TMAX * HDIM],      g_xl [(size_t)TMAX * HDIM];
__device__ __nv_bfloat16 g_w1h[(size_t)NE * FDIM * HDIM], g_w1l[(size_t)NE * FDIM * HDIM];
__device__ __nv_bfloat16 g_w3h[(size_t)NE * FDIM * HDIM], g_w3l[(size_t)NE * FDIM * HDIM];
__device__ __nv_bfloat16 g_w2h[(size_t)NE * HDIM * FDIM], g_w2l[(size_t)NE * HDIM * FDIM];
__device__ float g_a1[(size_t)NE * TMAX * FDIM];
__device__ __nv_bfloat16 g_hh [(size_t)NE * TMAX * FDIM], g_hl [(size_t)NE * TMAX * FDIM];
__device__ float g_o [(size_t)NE * TMAX * HDIM];

__device__ __forceinline__ uint32_t smem_u32(const void* p) {
    uint32_t a;
    asm("{ .reg .u64 t; cvta.to.shared.u64 t, %1; cvt.u32.u64 %0, t; }" : "=r"(a) : "l"(p));
    return a;
}

#define LDM4(r, addr) \
    asm volatile("ldmatrix.sync.aligned.m8n8.x4.shared.b16 {%0,%1,%2,%3}, [%4];" \
        : "=r"((r)[0]), "=r"((r)[1]), "=r"((r)[2]), "=r"((r)[3]) : "r"(addr))

#define MMA(d, a, b) \
    asm volatile("mma.sync.aligned.m16n8k16.row.col.f32.bf16.bf16.f32 " \
        "{%0,%1,%2,%3}, {%4,%5,%6,%7}, {%8,%9}, {%0,%1,%2,%3};" \
        : "+f"((d)[0]), "+f"((d)[1]), "+f"((d)[2]), "+f"((d)[3]) \
        : "r"((a)[0]), "r"((a)[1]), "r"((a)[2]), "r"((a)[3]), "r"((b)[0]), "r"((b)[1]))

#define CP_ASYNC(dst, src) \
    asm volatile("cp.async.cg.shared.global [%0], [%1], 16;" :: "r"(dst), "l"(src))
#define CP_COMMIT() asm volatile("cp.async.commit_group;")
#define CP_WAIT0()  asm volatile("cp.async.wait_group 0;")

__device__ __forceinline__ uint16_t bfu(__nv_bfloat16 b) { return __bfloat16_as_ushort(b); }

// ---------------- fp32 -> bf16 hi/lo conversion ----------------
__global__ void __launch_bounds__(256) k_cvt(const float4* __restrict__ s,
                                             uint2* __restrict__ hi, uint2* __restrict__ lo,
                                             int n4) {
    int i = blockIdx.x * 256 + threadIdx.x;
    if (i >= n4) return;
    float4 f = s[i];
    __nv_bfloat16 h0 = __float2bfloat16_rn(f.x), h1 = __float2bfloat16_rn(f.y);
    __nv_bfloat16 h2 = __float2bfloat16_rn(f.z), h3 = __float2bfloat16_rn(f.w);
    __nv_bfloat16 l0 = __float2bfloat16_rn(f.x - __bfloat162float(h0));
    __nv_bfloat16 l1 = __float2bfloat16_rn(f.y - __bfloat162float(h1));
    __nv_bfloat16 l2 = __float2bfloat16_rn(f.z - __bfloat162float(h2));
    __nv_bfloat16 l3 = __float2bfloat16_rn(f.w - __bfloat162float(h3));
    uint2 H, L;
    H.x = (uint32_t)bfu(h0) | ((uint32_t)bfu(h1) << 16);
    H.y = (uint32_t)bfu(h2) | ((uint32_t)bfu(h3) << 16);
    L.x = (uint32_t)bfu(l0) | ((uint32_t)bfu(l1) << 16);
    L.y = (uint32_t)bfu(l2) | ((uint32_t)bfu(l3) << 16);
    hi[i] = H;  lo[i] = L;
}

// ---------------- routing ----------------
__global__ void k_zero() { if (threadIdx.x < NE) g_count[threadIdx.x] = 0; }

__global__ void k_gate(const float* __restrict__ x, const float* __restrict__ gw) {
    int t = blockIdx.x, tid = threadIdx.x;
    const float* xr = x + (size_t)t * HDIM;
    float acc[NE];
#pragma unroll
    for (int e = 0; e < NE; e++) acc[e] = 0.f;
    for (int k = tid; k < HDIM; k += 128) {
        float xv = xr[k];
#pragma unroll
        for (int e = 0; e < NE; e++) acc[e] += xv * gw[e * HDIM + k];
    }
    __shared__ float s[NE][128];
#pragma unroll
    for (int e = 0; e < NE; e++) s[e][tid] = acc[e];
    __syncthreads();
    if (tid < NE) {
        float v = 0.f;
        for (int i = 0; i < 128; i++) v += s[tid][i];
        s[tid][0] = v;
    }
    __syncthreads();
    if (tid == 0) {
        float l[NE];
#pragma unroll
        for (int e = 0; e < NE; e++) l[e] = s[e][0];
        int i0 = 0;
#pragma unroll
        for (int e = 1; e < NE; e++) if (l[e] > l[i0]) i0 = e;
        int i1 = (i0 == 0) ? 1 : 0;
#pragma unroll
        for (int e = 0; e < NE; e++) if (e != i0 && l[e] > l[i1]) i1 = e;
        float w0 = 1.f / (1.f + expf(l[i1] - l[i0]));
        float w1 = 1.f - w0;
        int p0 = atomicAdd(&g_count[i0], 1);
        g_tok[i0 * TMAX + p0] = t;
        g_cslot[2 * t] = i0 * TMAX + p0;      g_cw[2 * t] = w0;
        int p1 = atomicAdd(&g_count[i1], 1);
        g_tok[i1 * TMAX + p1] = t;
        g_cslot[2 * t + 1] = i1 * TMAX + p1;  g_cw[2 * t + 1] = w1;
    }
}

// ---------------- grouped GEMM: cp.async 2-stage, 2 CTAs/SM, mma.sync hi/lo ----------------
template <int OP>
__global__ void __launch_bounds__(256, 2)
k_gemm() {
    constexpr int KD  = (OP == 2) ? FDIM : HDIM;
    constexpr int NW  = (OP == 2) ? HDIM : FDIM;
    constexpr int NIT = KD / KC;

    int e = blockIdx.z, cnt = g_count[e];
    int r0 = blockIdx.y * 128;
    if (r0 >= cnt) return;
    int c0 = blockIdx.x * 128;

    extern __shared__ char sm[];
    uint32_t sb = smem_u32(sm);
    int tid = threadIdx.x, lane = tid & 31, wid = tid >> 5;
    int wm = wid >> 2, wn = wid & 3;

    int* toks = (int*)(sm + NSTG * STG_B);
    if (OP != 2) {
        if (tid < 128) {
            int p = r0 + tid;
            toks[tid] = g_tok[e * TMAX + (p < cnt ? p : cnt - 1)];
        }
        __syncthreads();
    }

    // per-thread copy slots: row pair (row0, row0+64), 16B chunk ch
    int row0 = tid >> 2, ch = tid & 3;
    const char *pAh0, *pAh1, *pAl0, *pAl1, *pBh0, *pBl0;
    {
        size_t off0, off1;
        if (OP == 2) {
            off0 = ((size_t)e * TMAX + r0 + row0) * KD;
            off1 = ((size_t)e * TMAX + r0 + row0 + 64) * KD;
            pAh0 = (const char*)(g_hh + off0) + ch * 16;
            pAh1 = (const char*)(g_hh + off1) + ch * 16;
            pAl0 = (const char*)(g_hl + off0) + ch * 16;
            pAl1 = (const char*)(g_hl + off1) + ch * 16;
        } else {
            off0 = (size_t)toks[row0] * KD;
            off1 = (size_t)toks[row0 + 64] * KD;
            pAh0 = (const char*)(g_xh + off0) + ch * 16;
            pAh1 = (const char*)(g_xh + off1) + ch * 16;
            pAl0 = (const char*)(g_xl + off0) + ch * 16;
            pAl1 = (const char*)(g_xl + off1) + ch * 16;
        }
        size_t boff = ((size_t)e * NW + c0 + row0) * KD;
        const __nv_bfloat16 *bh, *bl;
        if (OP == 0)      { bh = g_w1h; bl = g_w1l; }
        else if (OP == 1) { bh = g_w3h; bl = g_w3l; }
        else              { bh = g_w2h; bl = g_w2l; }
        pBh0 = (const char*)(bh + boff) + ch * 16;
        pBl0 = (const char*)(bl + boff) + ch * 16;
    }
    const uint32_t dstb = (uint32_t)(row0 * (TSTR * 2) + ch * 16);
    constexpr size_t BROWS = (size_t)64 * KD * 2;   // +64 rows in B (bytes)

    float acc[4][4][4];
#pragma unroll
    for (int a = 0; a < 4; a++)
#pragma unroll
        for (int b = 0; b < 4; b++)
#pragma unroll
            for (int c = 0; c < 4; c++) acc[a][b][c] = 0.f;

    auto ISSUE = [&](int slot, int it) {
        uint32_t d = sb + (uint32_t)slot * STG_B + dstb;
        size_t s = (size_t)it * (KC * 2);           // 64B per stage along K
        CP_ASYNC(d,                     pAh0 + s);
        CP_ASYNC(d + 64 * (TSTR * 2),   pAh1 + s);
        CP_ASYNC(d + AST,               pAl0 + s);
        CP_ASYNC(d + AST + 64 * (TSTR * 2), pAl1 + s);
        CP_ASYNC(d + 2 * AST,               pBh0 + s);
        CP_ASYNC(d + 2 * AST + 64 * (TSTR * 2), pBh0 + BROWS + s);
        CP_ASYNC(d + 3 * AST,               pBl0 + s);
        CP_ASYNC(d + 3 * AST + 64 * (TSTR * 2), pBl0 + BROWS + s);
        CP_COMMIT();
    };

    auto COMPUTE = [&](int slot) {
        uint32_t base = sb + (uint32_t)slot * STG_B;
#pragma unroll
        for (int ks = 0; ks < 2; ks++) {
            uint32_t Ah[4][4], Al[4][4];
            uint32_t la = ((lane & 15) * TSTR + ((lane >> 4) << 3) + ks * 16) * 2;
#pragma unroll
            for (int mf = 0; mf < 4; mf++) {
                uint32_t ad = base + (wm * 64 + mf * 16) * (TSTR * 2) + la;
                LDM4(Ah[mf], ad);
                LDM4(Al[mf], ad + AST);
            }
            uint32_t lb = (((lane & 7) + ((lane >> 4) << 3)) * TSTR
                           + ks * 16 + ((lane >> 3) & 1) * 8) * 2;
#pragma unroll
            for (int nf2 = 0; nf2 < 2; nf2++) {
                uint32_t bd = base + 2 * AST + (wn * 32 + nf2 * 16) * (TSTR * 2) + lb;
                uint32_t th[4], tl[4];
                LDM4(th, bd);
                LDM4(tl, bd + AST);
#pragma unroll
                for (int half = 0; half < 2; half++) {
                    int nf = 2 * nf2 + half;
                    uint32_t Bh[2] = {th[2 * half], th[2 * half + 1]};
                    uint32_t Bl[2] = {tl[2 * half], tl[2 * half + 1]};
#pragma unroll
                    for (int mf = 0; mf < 4; mf++) {
                        MMA(acc[mf][nf], Ah[mf], Bh);
                        MMA(acc[mf][nf], Ah[mf], Bl);
                        MMA(acc[mf][nf], Al[mf], Bh);
                    }
                }
            }
        }
    };

    ISSUE(0, 0);
    for (int it = 0; it < NIT; it++) {
        CP_WAIT0();            // stage `it` landed
        __syncthreads();       // visible to all; prior compute done before reuse
        if (it + 1 < NIT) ISSUE((it + 1) & 1, it + 1);
        COMPUTE(it & 1);
    }

    // ---------------- epilogue ----------------
    int rb = r0 + wm * 64;
    int cb = c0 + wn * 32 + (lane & 3) * 2;
#pragma unroll
    for (int mf = 0; mf < 4; mf++) {
#pragma unroll
        for (int h = 0; h < 2; h++) {
            int row = rb + mf * 16 + (lane >> 2) + 8 * h;
            if (row >= cnt) continue;
            size_t rowbase = ((size_t)e * TMAX + row) * (size_t)NW;
#pragma unroll
            for (int nf = 0; nf < 4; nf++) {
                size_t idx = rowbase + (cb + nf * 8);
                float vx = acc[mf][nf][2 * h], vy = acc[mf][nf][2 * h + 1];
                if (OP == 0) {
                    *(float2*)&g_a1[idx] = make_float2(vx, vy);
                } else if (OP == 1) {
                    float2 a1 = *(const float2*)&g_a1[idx];
                    float ox = vx * a1.x / (1.f + __expf(-a1.x));
                    float oy = vy * a1.y / (1.f + __expf(-a1.y));
                    __nv_bfloat16 hx = __float2bfloat16_rn(ox), hy = __float2bfloat16_rn(oy);
                    __nv_bfloat16 lx = __float2bfloat16_rn(ox - __bfloat162float(hx));
                    __nv_bfloat16 ly = __float2bfloat16_rn(oy - __bfloat162float(hy));
                    *(uint32_t*)&g_hh[idx] = (uint32_t)bfu(hx) | ((uint32_t)bfu(hy) << 16);
                    *(uint32_t*)&g_hl[idx] = (uint32_t)bfu(lx) | ((uint32_t)bfu(ly) << 16);
                } else {
                    *(float2*)&g_o[idx] = make_float2(vx, vy);
                }
            }
        }
    }
}

// ---------------- combine ----------------
__global__ void __launch_bounds__(256) k_comb(float* __restrict__ out) {
    int i  = blockIdx.x * 256 + threadIdx.x;
    int t  = i >> 9;
    int c4 = (i & 511) << 2;
    int   s0 = g_cslot[2 * t],  s1 = g_cslot[2 * t + 1];
    float w0 = g_cw[2 * t],     w1 = g_cw[2 * t + 1];
    float4 a = *(const float4*)(g_o + (size_t)s0 * HDIM + c4);
    float4 b = *(const float4*)(g_o + (size_t)s1 * HDIM + c4);
    float4 o;
    o.x = w0 * a.x + w1 * b.x;  o.y = w0 * a.y + w1 * b.y;
    o.z = w0 * a.z + w1 * b.z;  o.w = w0 * a.w + w1 * b.w;
    *(float4*)(out + (size_t)t * HDIM + c4) = o;
}

// ---------------- host ----------------
extern "C" void kernel_launch(void* const* d_in, const int* in_sizes, int n_in,
                              void* d_out, int out_size) {
    const float* x  = (const float*)d_in[0];
    const float* gw = (const float*)d_in[1];
    const float* w1 = (const float*)d_in[2];
    const float* w2 = (const float*)d_in[3];
    const float* w3 = (const float*)d_in[4];
    float* out = (float*)d_out;

    cudaFuncSetAttribute(k_gemm<0>, cudaFuncAttributeMaxDynamicSharedMemorySize, SMEM_SZ);
    cudaFuncSetAttribute(k_gemm<1>, cudaFuncAttributeMaxDynamicSharedMemorySize, SMEM_SZ);
    cudaFuncSetAttribute(k_gemm<2>, cudaFuncAttributeMaxDynamicSharedMemorySize, SMEM_SZ);

    void *xh, *xl, *w1h, *w1l, *w3h, *w3l, *w2h, *w2l;
    cudaGetSymbolAddress(&xh,  g_xh);  cudaGetSymbolAddress(&xl,  g_xl);
    cudaGetSymbolAddress(&w1h, g_w1h); cudaGetSymbolAddress(&w1l, g_w1l);
    cudaGetSymbolAddress(&w3h, g_w3h); cudaGetSymbolAddress(&w3l, g_w3l);
    cudaGetSymbolAddress(&w2h, g_w2h); cudaGetSymbolAddress(&w2l, g_w2l);

    const int nx4 = TMAX * HDIM / 4;
    const int nw4 = NE * FDIM * HDIM / 4;

    k_zero<<<1, 32>>>();
    k_gate<<<TMAX, 128>>>(x, gw);
    k_cvt<<<(nx4 + 255) / 256, 256>>>((const float4*)x,  (uint2*)xh,  (uint2*)xl,  nx4);
    k_cvt<<<(nw4 + 255) / 256, 256>>>((const float4*)w1, (uint2*)w1h, (uint2*)w1l, nw4);
    k_cvt<<<(nw4 + 255) / 256, 256>>>((const float4*)w3, (uint2*)w3h, (uint2*)w3l, nw4);
    k_cvt<<<(nw4 + 255) / 256, 256>>>((const float4*)w2, (uint2*)w2h, (uint2*)w2l, nw4);
    k_gemm<0><<<dim3(FDIM / 128, TMAX / 128, NE), 256, SMEM_SZ>>>();
    k_gemm<1><<<dim3(FDIM / 128, TMAX / 128, NE), 256, SMEM_SZ>>>();
    k_gemm<2><<<dim3(HDIM / 128, TMAX / 128, NE), 256, SMEM_SZ>>>();
    k_comb<<<TMAX * (HDIM / 4) / 256, 256>>>(out);
}